// round 1
// baseline (speedup 1.0000x reference)
#include <cuda_runtime.h>
#include <cuda_bf16.h>
#include <cstdint>

#define N_TOK   16384
#define DIM     1024
#define NEXP    64
#define TOPK    2
#define CAP     640

// ---------------- persistent scratch (__device__ globals; no allocs) ----------
__device__ int   g_ef[2 * N_TOK];        // expert id per flat entry f = j*N + n
__device__ float g_gf[2 * N_TOK];        // gate per flat entry
__device__ int   g_slot_tok[NEXP * CAP]; // token index per (expert, slot)
__device__ float g_slot_gate[NEXP * CAP];// gate per (expert, slot)
__device__ int   g_cnt[NEXP];            // tokens assigned per expert (pre-clamp)

// ---------------- K0: zero output --------------------------------------------
__global__ void zero_kernel(float4* __restrict__ out) {
    int idx = blockIdx.x * blockDim.x + threadIdx.x;  // 1,048,576 threads
#pragma unroll
    for (int i = 0; i < 4; i++)
        out[idx + i * 1048576] = make_float4(0.f, 0.f, 0.f, 0.f);
}

// ---------------- K1: router (logits GEMM + top-2 + softmax) ------------------
// 64 tokens x 64 experts per block, 256 threads, 4x4 per thread, TK=16.
__global__ void router_kernel(const float* __restrict__ x,
                              const float* __restrict__ Wr,
                              const float* __restrict__ br) {
    __shared__ float xs[16][64];   // [d][token]
    __shared__ float ws[16][64];   // [d][expert]
    __shared__ float sm[64 * 65];  // logits, padded stride

    const int tid = threadIdx.x;
    const int tx = tid & 15, ty = tid >> 4;
    const int tok0 = blockIdx.x * 64;

    const int lt = tid >> 2;       // x-load row 0..63
    const int lq = tid & 3;        // x-load quad
    const int wd = tid >> 4;       // Wr-load row 0..15
    const int we = (tid & 15) * 4; // Wr-load col

    float acc[4][4] = {};

    for (int d0 = 0; d0 < DIM; d0 += 16) {
        float4 xv = *(const float4*)&x[(size_t)(tok0 + lt) * DIM + d0 + lq * 4];
        float4 wv = *(const float4*)&Wr[(size_t)(d0 + wd) * NEXP + we];
        __syncthreads();
        xs[lq * 4 + 0][lt] = xv.x; xs[lq * 4 + 1][lt] = xv.y;
        xs[lq * 4 + 2][lt] = xv.z; xs[lq * 4 + 3][lt] = xv.w;
        *(float4*)&ws[wd][we] = wv;
        __syncthreads();
#pragma unroll
        for (int kk = 0; kk < 16; kk++) {
            float a[4], b[4];
#pragma unroll
            for (int i = 0; i < 4; i++) a[i] = xs[kk][ty * 4 + i];
#pragma unroll
            for (int j = 0; j < 4; j++) b[j] = ws[kk][tx * 4 + j];
#pragma unroll
            for (int i = 0; i < 4; i++)
#pragma unroll
                for (int j = 0; j < 4; j++) acc[i][j] += a[i] * b[j];
        }
    }
    __syncthreads();
#pragma unroll
    for (int i = 0; i < 4; i++)
#pragma unroll
        for (int j = 0; j < 4; j++)
            sm[(ty * 4 + i) * 65 + tx * 4 + j] = acc[i][j] + br[tx * 4 + j];
    __syncthreads();

    if (tid < 64) {
        const int t = tid;
        float v1 = -3.402823466e+38f, v2 = -3.402823466e+38f;
        int i1 = 0, i2 = 0;
#pragma unroll 4
        for (int e = 0; e < NEXP; e++) {
            float v = sm[t * 65 + e];
            if (v > v1) { v2 = v1; i2 = i1; v1 = v; i1 = e; }
            else if (v > v2) { v2 = v; i2 = e; }
        }
        float texp = expf(v2 - v1);          // v2 <= v1, stable
        float inv = 1.f / (1.f + texp);
        int n = tok0 + t;
        g_ef[n]          = i1;
        g_ef[N_TOK + n]  = i2;
        g_gf[n]          = inv;
        g_gf[N_TOK + n]  = texp * inv;
    }
}

// ---------------- K2: deterministic per-expert slot scan ----------------------
// One block per expert; exact reproduction of the reference's cumsum over the
// k-major flat ordering.
__global__ void scan_kernel() {
    const int e = blockIdx.x;
    const int tid = threadIdx.x;          // 256 threads
    __shared__ int sc[256];
    const int PER = (2 * N_TOK) / 256;    // 128
    const int base = tid * PER;

    int c = 0;
    for (int i = 0; i < PER; i++) c += (g_ef[base + i] == e);
    sc[tid] = c;
    __syncthreads();
    // inclusive Hillis-Steele scan
    for (int off = 1; off < 256; off <<= 1) {
        int v = sc[tid];
        int add = (tid >= off) ? sc[tid - off] : 0;
        __syncthreads();
        sc[tid] = v + add;
        __syncthreads();
    }
    int s = sc[tid] - c;                  // exclusive prefix
    for (int i = 0; i < PER; i++) {
        int f = base + i;
        if (g_ef[f] == e) {
            if (s < CAP) {
                g_slot_tok[e * CAP + s]  = (f >= N_TOK) ? (f - N_TOK) : f;
                g_slot_gate[e * CAP + s] = g_gf[f];
            }
            s++;
        }
    }
    if (tid == 255) g_cnt[e] = sc[255];
}

// ---------------- K3: grouped expert GEMM (gather-A) + ReLU + fused combine ---
// Tile 128x128, TK=16, 256 threads, 8x8 accum/thread. A rows gathered from x
// via slot->token map; epilogue scatters gate*relu(acc) into out with atomics
// (<=2 contributions per element -> deterministic).
__global__ void moe_gemm_kernel(const float* __restrict__ x,
                                const float* __restrict__ We,
                                float* __restrict__ out) {
    __shared__ float as[16][128];
    __shared__ float bs[16][128];
    __shared__ int   tok_s[128];
    __shared__ float gate_s[128];

    const int e = blockIdx.z;
    const int cnt_e = min(g_cnt[e], CAP);
    const int m0 = blockIdx.y * 128;
    if (m0 >= cnt_e) return;
    const int n0 = blockIdx.x * 128;
    const int tid = threadIdx.x;

    if (tid < 128) {
        int r = m0 + tid;
        bool v = r < cnt_e;
        tok_s[tid]  = v ? g_slot_tok[e * CAP + r]  : 0;
        gate_s[tid] = v ? g_slot_gate[e * CAP + r] : 0.f;
    }
    __syncthreads();

    const int arow = tid >> 1;
    const int acol = (tid & 1) * 8;
    const float* xrow = x + (size_t)tok_s[arow] * DIM + acol;

    const int brow = tid >> 4;
    const int bcol = (tid & 15) * 8;
    const float* wptr = We + (size_t)e * DIM * DIM + (size_t)brow * DIM + n0 + bcol;

    const int tx = tid & 15, ty = tid >> 4;
    float acc[8][8] = {};

    for (int d0 = 0; d0 < DIM; d0 += 16) {
        float4 a0 = *(const float4*)(xrow + d0);
        float4 a1 = *(const float4*)(xrow + d0 + 4);
        float4 b0 = *(const float4*)(wptr + (size_t)d0 * DIM);
        float4 b1 = *(const float4*)(wptr + (size_t)d0 * DIM + 4);
        __syncthreads();
        as[acol + 0][arow] = a0.x; as[acol + 1][arow] = a0.y;
        as[acol + 2][arow] = a0.z; as[acol + 3][arow] = a0.w;
        as[acol + 4][arow] = a1.x; as[acol + 5][arow] = a1.y;
        as[acol + 6][arow] = a1.z; as[acol + 7][arow] = a1.w;
        *(float4*)&bs[brow][bcol]     = b0;
        *(float4*)&bs[brow][bcol + 4] = b1;
        __syncthreads();
#pragma unroll
        for (int kk = 0; kk < 16; kk++) {
            float a[8], b[8];
#pragma unroll
            for (int i = 0; i < 4; i++) {
                a[i]     = as[kk][ty * 4 + i];
                a[i + 4] = as[kk][64 + ty * 4 + i];
                b[i]     = bs[kk][tx * 4 + i];
                b[i + 4] = bs[kk][64 + tx * 4 + i];
            }
#pragma unroll
            for (int i = 0; i < 8; i++)
#pragma unroll
                for (int j = 0; j < 8; j++) acc[i][j] += a[i] * b[j];
        }
    }

    // epilogue: gated ReLU scatter-add into out[token]
#pragma unroll
    for (int i = 0; i < 8; i++) {
        int rl = (i < 4) ? (ty * 4 + i) : (64 + ty * 4 + (i - 4));
        int r = m0 + rl;
        if (r < cnt_e) {
            int   tokn = tok_s[rl];
            float g    = gate_s[rl];
            float* orow = out + (size_t)tokn * DIM + n0;
#pragma unroll
            for (int j = 0; j < 8; j++) {
                int cl = (j < 4) ? (tx * 4 + j) : (64 + tx * 4 + (j - 4));
                atomicAdd(orow + cl, g * fmaxf(acc[i][j], 0.f));
            }
        }
    }
}

// ---------------- launch ------------------------------------------------------
extern "C" void kernel_launch(void* const* d_in, const int* in_sizes, int n_in,
                              void* d_out, int out_size) {
    // Identify inputs robustly by element count (all distinct).
    const float *x = nullptr, *Wr = nullptr, *br = nullptr, *We = nullptr;
    for (int i = 0; i < n_in; i++) {
        switch (in_sizes[i]) {
            case N_TOK * DIM:        x  = (const float*)d_in[i]; break;  // 16777216
            case DIM * NEXP:         Wr = (const float*)d_in[i]; break;  // 65536
            case NEXP:               br = (const float*)d_in[i]; break;  // 64
            default:
                if (in_sizes[i] == NEXP * DIM * DIM) We = (const float*)d_in[i];
                break;
        }
    }
    float* out = (float*)d_out;

    zero_kernel<<<4096, 256>>>((float4*)out);
    router_kernel<<<N_TOK / 64, 256>>>(x, Wr, br);
    scan_kernel<<<NEXP, 256>>>();
    dim3 grid(DIM / 128, (CAP + 127) / 128, NEXP);   // 8 x 5 x 64
    moe_gemm_kernel<<<grid, 256>>>(x, We, out);
}

// round 5
// speedup vs baseline: 3.5099x; 3.5099x over previous
#include <cuda_runtime.h>
#include <cuda_fp16.h>
#include <cstdint>

#define N_TOK   16384
#define DIM     1024
#define NEXP    64
#define CAP     640

#define BM 128
#define BN 128
#define KC 32
#define NK (DIM / KC)                 // 32 K-chunks
#define STAGES 3
#define LDS_H 40                      // halves per smem row (32 + 8 pad) = 80 B
#define STG_BYTES (BM * LDS_H * 2)    // 10240 per operand per stage
#define SMEM_BYTES (STAGES * 2 * STG_BYTES)  // 61440

// ---------------- persistent scratch ------------------------------------------
__device__ int   g_ef[2 * N_TOK];
__device__ float g_gf[2 * N_TOK];
__device__ int   g_slot_tok[NEXP * CAP];
__device__ float g_slot_gate[NEXP * CAP];
__device__ int   g_cnt[NEXP];
__device__ __align__(1024) __half g_A[(size_t)NEXP * CAP * DIM];   // [e][slot][k]
__device__ __align__(1024) __half g_B[(size_t)NEXP * DIM * DIM];   // [e][n][k]

// ---------------- helpers -----------------------------------------------------
__device__ __forceinline__ uint32_t smem_u32(const void* p) {
    uint32_t a;
    asm("{ .reg .u64 t; cvta.to.shared.u64 t, %1; cvt.u32.u64 %0, t; }"
        : "=r"(a) : "l"(p));
    return a;
}
__device__ __forceinline__ void cp16(uint32_t s, const void* g) {
    asm volatile("cp.async.cg.shared.global [%0], [%1], 16;" :: "r"(s), "l"(g));
}
#define CP_COMMIT() asm volatile("cp.async.commit_group;" ::: "memory")

__device__ __forceinline__ void ldsm_x4(uint32_t* r, uint32_t addr) {
    asm volatile("ldmatrix.sync.aligned.m8n8.x4.shared.b16 {%0,%1,%2,%3}, [%4];"
                 : "=r"(r[0]), "=r"(r[1]), "=r"(r[2]), "=r"(r[3]) : "r"(addr));
}
__device__ __forceinline__ void ldsm_x2(uint32_t* r, uint32_t addr) {
    asm volatile("ldmatrix.sync.aligned.m8n8.x2.shared.b16 {%0,%1}, [%2];"
                 : "=r"(r[0]), "=r"(r[1]) : "r"(addr));
}
__device__ __forceinline__ void mma16816(float* c, const uint32_t* a,
                                         const uint32_t* b) {
    asm volatile(
        "mma.sync.aligned.m16n8k16.row.col.f32.f16.f16.f32 "
        "{%0,%1,%2,%3}, {%4,%5,%6,%7}, {%8,%9}, {%0,%1,%2,%3};"
        : "+f"(c[0]), "+f"(c[1]), "+f"(c[2]), "+f"(c[3])
        : "r"(a[0]), "r"(a[1]), "r"(a[2]), "r"(a[3]), "r"(b[0]), "r"(b[1]));
}

// ---------------- K0: zero output --------------------------------------------
__global__ void zero_kernel(float4* __restrict__ out) {
    int idx = blockIdx.x * blockDim.x + threadIdx.x;
#pragma unroll
    for (int i = 0; i < 4; i++)
        out[idx + i * 1048576] = make_float4(0.f, 0.f, 0.f, 0.f);
}

// ---------------- K1: router (fp32 GEMM + top-2 + softmax) --------------------
__global__ void router_kernel(const float* __restrict__ x,
                              const float* __restrict__ Wr,
                              const float* __restrict__ br) {
    __shared__ float xs[16][64];
    __shared__ float ws[16][64];
    __shared__ float sm[64 * 65];

    const int tid = threadIdx.x;
    const int tx = tid & 15, ty = tid >> 4;
    const int tok0 = blockIdx.x * 64;
    const int lt = tid >> 2, lq = tid & 3;
    const int wd = tid >> 4, we = (tid & 15) * 4;

    float acc[4][4] = {};
    for (int d0 = 0; d0 < DIM; d0 += 16) {
        float4 xv = *(const float4*)&x[(size_t)(tok0 + lt) * DIM + d0 + lq * 4];
        float4 wv = *(const float4*)&Wr[(size_t)(d0 + wd) * NEXP + we];
        __syncthreads();
        xs[lq * 4 + 0][lt] = xv.x; xs[lq * 4 + 1][lt] = xv.y;
        xs[lq * 4 + 2][lt] = xv.z; xs[lq * 4 + 3][lt] = xv.w;
        *(float4*)&ws[wd][we] = wv;
        __syncthreads();
#pragma unroll
        for (int kk = 0; kk < 16; kk++) {
            float a[4], b[4];
#pragma unroll
            for (int i = 0; i < 4; i++) a[i] = xs[kk][ty * 4 + i];
#pragma unroll
            for (int j = 0; j < 4; j++) b[j] = ws[kk][tx * 4 + j];
#pragma unroll
            for (int i = 0; i < 4; i++)
#pragma unroll
                for (int j = 0; j < 4; j++) acc[i][j] += a[i] * b[j];
        }
    }
    __syncthreads();
#pragma unroll
    for (int i = 0; i < 4; i++)
#pragma unroll
        for (int j = 0; j < 4; j++)
            sm[(ty * 4 + i) * 65 + tx * 4 + j] = acc[i][j] + br[tx * 4 + j];
    __syncthreads();

    if (tid < 64) {
        const int t = tid;
        float v1 = -3.402823466e+38f, v2 = -3.402823466e+38f;
        int i1 = 0, i2 = 0;
#pragma unroll 4
        for (int e = 0; e < NEXP; e++) {
            float v = sm[t * 65 + e];
            if (v > v1) { v2 = v1; i2 = i1; v1 = v; i1 = e; }
            else if (v > v2) { v2 = v; i2 = e; }
        }
        float texp = expf(v2 - v1);
        float inv = 1.f / (1.f + texp);
        int n = tok0 + t;
        g_ef[n]         = i1;
        g_ef[N_TOK + n] = i2;
        g_gf[n]         = inv;
        g_gf[N_TOK + n] = texp * inv;
    }
}

// ---------------- K2: deterministic per-expert slot scan ----------------------
__global__ void scan_kernel() {
    const int e = blockIdx.x;
    const int tid = threadIdx.x;
    __shared__ int sc[256];
    const int PER = (2 * N_TOK) / 256;
    const int base = tid * PER;

    int c = 0;
    for (int i = 0; i < PER; i++) c += (g_ef[base + i] == e);
    sc[tid] = c;
    __syncthreads();
    for (int off = 1; off < 256; off <<= 1) {
        int v = sc[tid];
        int add = (tid >= off) ? sc[tid - off] : 0;
        __syncthreads();
        sc[tid] = v + add;
        __syncthreads();
    }
    int s = sc[tid] - c;
    for (int i = 0; i < PER; i++) {
        int f = base + i;
        if (g_ef[f] == e) {
            if (s < CAP) {
                g_slot_tok[e * CAP + s]  = (f >= N_TOK) ? (f - N_TOK) : f;
                g_slot_gate[e * CAP + s] = g_gf[f];
            }
            s++;
        }
    }
    if (tid == 255) g_cnt[e] = sc[255];
}

// ---------------- K3a: convert+transpose We -> fp16 [e][n][k] -----------------
__global__ void convW_kernel(const float* __restrict__ We) {
    __shared__ float s[32][65];   // [h][d]
    const int e = blockIdx.z;
    const int h0 = blockIdx.x * 32, d0 = blockIdx.y * 64;
    const int tx = threadIdx.x, ty = threadIdx.y;   // (32, 8)
    const float* W = We + (size_t)e * DIM * DIM;
#pragma unroll
    for (int j = 0; j < 8; j++) {
        int dd = ty + j * 8;
        s[tx][dd] = W[(size_t)(d0 + dd) * DIM + h0 + tx];
    }
    __syncthreads();
#pragma unroll
    for (int j = 0; j < 4; j++) {
        int hh = ty + j * 8;
        __half2 hv = __floats2half2_rn(s[hh][2 * tx], s[hh][2 * tx + 1]);
        *(__half2*)(g_B + (size_t)e * DIM * DIM + (size_t)(h0 + hh) * DIM +
                    d0 + 2 * tx) = hv;
    }
}

// ---------------- K3b: pack dispatched token rows -> fp16 ---------------------
__global__ void packA_kernel(const float* __restrict__ x) {
    const int row = blockIdx.x;              // e*CAP + slot
    const int e = row / CAP, s = row % CAP;
    if (s >= min(g_cnt[e], CAP)) return;
    const int tok = g_slot_tok[row];
    const int t = threadIdx.x * 8;           // 128 threads x 8 elems
    const float4* src = (const float4*)(x + (size_t)tok * DIM + t);
    float4 f0 = src[0], f1 = src[1];
    uint4 u;
    __half2* ph = (__half2*)&u;
    ph[0] = __floats2half2_rn(f0.x, f0.y);
    ph[1] = __floats2half2_rn(f0.z, f0.w);
    ph[2] = __floats2half2_rn(f1.x, f1.y);
    ph[3] = __floats2half2_rn(f1.z, f1.w);
    *(uint4*)(g_A + (size_t)row * DIM + t) = u;
}

// ---------------- K4: mma.sync fp16 grouped GEMM + fused gated ReLU combine ---
extern __shared__ __align__(128) char dsmem[];

__global__ void __launch_bounds__(256, 2)
moe_mma_kernel(float* __restrict__ out) {
    const int e = blockIdx.z;
    const int cnt = min(g_cnt[e], CAP);
    const int m0 = blockIdx.y * BM;
    if (m0 >= cnt) return;
    const int n0 = blockIdx.x * BN;
    const int tid = threadIdx.x;
    const int lane = tid & 31, wid = tid >> 5;
    const int wm = (wid & 1) * 64, wn = (wid >> 1) * 32;

    __shared__ int   tok_s[BM];
    __shared__ float gate_s[BM];
    if (tid < BM) {
        int r = m0 + tid;
        bool v = r < cnt;
        tok_s[tid]  = v ? g_slot_tok[e * CAP + r] : 0;
        gate_s[tid] = v ? g_slot_gate[e * CAP + r] : 0.f;
    }

    const uint32_t sbase = smem_u32(dsmem);
    const __half* Ag = g_A + ((size_t)e * CAP + m0) * DIM;
    const __half* Bg = g_B + ((size_t)e * DIM + n0) * DIM;

    // loader mapping: 512 16B-copies per operand-pair per stage, 2 per thread
    const int lr0 = tid >> 2, lq = tid & 3;          // rows 0..63
    const uint32_t loff0 = (uint32_t)(lr0 * 80 + lq * 16);
    const uint32_t loff1 = (uint32_t)((lr0 + 64) * 80 + lq * 16);

#define LOAD_STAGE(s, kc) do {                                                \
        uint32_t sA = sbase + (s) * 2 * STG_BYTES;                            \
        uint32_t sB = sA + STG_BYTES;                                         \
        const __half* Ak = Ag + (kc) * KC + lq * 8;                           \
        const __half* Bk = Bg + (kc) * KC + lq * 8;                           \
        cp16(sA + loff0, Ak + (size_t)lr0 * DIM);                             \
        cp16(sA + loff1, Ak + (size_t)(lr0 + 64) * DIM);                      \
        cp16(sB + loff0, Bk + (size_t)lr0 * DIM);                             \
        cp16(sB + loff1, Bk + (size_t)(lr0 + 64) * DIM);                      \
    } while (0)

    LOAD_STAGE(0, 0); CP_COMMIT();
    LOAD_STAGE(1, 1); CP_COMMIT();

    float acc[4][4][4] = {};

    // precomputed ldmatrix lane offsets (bytes)
    const uint32_t aoffs = (uint32_t)((wm + (lane & 15)) * 80 + (lane >> 4) * 16);
    const uint32_t boffs = (uint32_t)((wn + (lane & 7)) * 80 + ((lane >> 3) & 1) * 16);

    for (int kc = 0; kc < NK; kc++) {
        const int buf = kc % STAGES;
        asm volatile("cp.async.wait_group 1;" ::: "memory");
        __syncthreads();
        if (kc + 2 < NK) LOAD_STAGE((kc + 2) % STAGES, kc + 2);
        CP_COMMIT();

        const uint32_t sA = sbase + buf * 2 * STG_BYTES;
        const uint32_t sB = sA + STG_BYTES;
#pragma unroll
        for (int k16 = 0; k16 < KC; k16 += 16) {
            uint32_t a[4][4], b[4][2];
#pragma unroll
            for (int mi = 0; mi < 4; mi++)
                ldsm_x4(a[mi], sA + aoffs + (uint32_t)(mi * 16 * 80 + k16 * 2));
#pragma unroll
            for (int ni = 0; ni < 4; ni++)
                ldsm_x2(b[ni], sB + boffs + (uint32_t)(ni * 8 * 80 + k16 * 2));
#pragma unroll
            for (int mi = 0; mi < 4; mi++)
#pragma unroll
                for (int ni = 0; ni < 4; ni++)
                    mma16816(acc[mi][ni], a[mi], b[ni]);
        }
    }

    // fused epilogue: out[token] += gate * relu(acc)  (<=2 contributions/elem)
#pragma unroll
    for (int mi = 0; mi < 4; mi++) {
        const int rbase = wm + mi * 16 + (lane >> 2);
#pragma unroll
        for (int h = 0; h < 2; h++) {
            const int rr = rbase + h * 8;
            if (m0 + rr < cnt) {
                const float g = gate_s[rr];
                float* orow = out + (size_t)tok_s[rr] * DIM + n0 + wn +
                              (lane & 3) * 2;
#pragma unroll
                for (int ni = 0; ni < 4; ni++) {
                    float2 v = make_float2(
                        g * fmaxf(acc[mi][ni][2 * h], 0.f),
                        g * fmaxf(acc[mi][ni][2 * h + 1], 0.f));
                    atomicAdd((float2*)(orow + ni * 8), v);
                }
            }
        }
    }
#undef LOAD_STAGE
}

// ---------------- launch ------------------------------------------------------
extern "C" void kernel_launch(void* const* d_in, const int* in_sizes, int n_in,
                              void* d_out, int out_size) {
    const float *x = nullptr, *Wr = nullptr, *br = nullptr, *We = nullptr;
    for (int i = 0; i < n_in; i++) {
        switch (in_sizes[i]) {
            case N_TOK * DIM: x  = (const float*)d_in[i]; break;
            case DIM * NEXP:  Wr = (const float*)d_in[i]; break;
            case NEXP:        br = (const float*)d_in[i]; break;
            default:
                if (in_sizes[i] == NEXP * DIM * DIM) We = (const float*)d_in[i];
                break;
        }
    }
    float* out = (float*)d_out;

    cudaFuncSetAttribute(moe_mma_kernel,
                         cudaFuncAttributeMaxDynamicSharedMemorySize, SMEM_BYTES);

    zero_kernel<<<4096, 256>>>((float4*)out);
    convW_kernel<<<dim3(32, 16, 64), dim3(32, 8)>>>(We);
    router_kernel<<<N_TOK / 64, 256>>>(x, Wr, br);
    scan_kernel<<<NEXP, 256>>>();
    packA_kernel<<<NEXP * CAP, 128>>>(x);
    dim3 grid(DIM / BN, (CAP + BM - 1) / BM, NEXP);   // 8 x 5 x 64
    moe_mma_kernel<<<grid, 256, SMEM_BYTES>>>(out);
}

// round 7
// speedup vs baseline: 3.5125x; 1.0008x over previous
#include <cuda_runtime.h>
#include <cuda_fp16.h>
#include <cstdint>

#define N_TOK   16384
#define DIM     1024
#define NEXP    64
#define CAP     640

#define BM 128
#define BN 256
#define KC 32
#define NK (DIM / KC)                 // 32 K-chunks
#define A_STG 10240                   // 128 rows * 80 B
#define B_STG 20480                   // 256 rows * 80 B
#define STG   (A_STG + B_STG)         // 30720
#define SMEM_BYTES (4 * STG)          // 122880, 4 stages

// ---------------- persistent scratch ------------------------------------------
__device__ int   g_ef[2 * N_TOK];
__device__ float g_gf[2 * N_TOK];
__device__ int   g_slot_tok[NEXP * CAP];
__device__ float g_slot_gate[NEXP * CAP];
__device__ int   g_cnt[NEXP];
__device__ __align__(1024) __half g_A[(size_t)NEXP * CAP * DIM];   // [e][slot][k]
__device__ __align__(1024) __half g_B[(size_t)NEXP * DIM * DIM];   // [e][n][k]

// ---------------- helpers -----------------------------------------------------
__device__ __forceinline__ uint32_t smem_u32(const void* p) {
    uint32_t a;
    asm("{ .reg .u64 t; cvta.to.shared.u64 t, %1; cvt.u32.u64 %0, t; }"
        : "=r"(a) : "l"(p));
    return a;
}
__device__ __forceinline__ void cp16(uint32_t s, const void* g) {
    asm volatile("cp.async.cg.shared.global [%0], [%1], 16;" :: "r"(s), "l"(g));
}
#define CP_COMMIT() asm volatile("cp.async.commit_group;" ::: "memory")

__device__ __forceinline__ void ldsm_x4(uint32_t* r, uint32_t addr) {
    asm volatile("ldmatrix.sync.aligned.m8n8.x4.shared.b16 {%0,%1,%2,%3}, [%4];"
                 : "=r"(r[0]), "=r"(r[1]), "=r"(r[2]), "=r"(r[3]) : "r"(addr));
}
__device__ __forceinline__ void ldsm_x2(uint32_t* r, uint32_t addr) {
    asm volatile("ldmatrix.sync.aligned.m8n8.x2.shared.b16 {%0,%1}, [%2];"
                 : "=r"(r[0]), "=r"(r[1]) : "r"(addr));
}
__device__ __forceinline__ void mma16816(float* c, const uint32_t* a,
                                         const uint32_t* b) {
    asm volatile(
        "mma.sync.aligned.m16n8k16.row.col.f32.f16.f16.f32 "
        "{%0,%1,%2,%3}, {%4,%5,%6,%7}, {%8,%9}, {%0,%1,%2,%3};"
        : "+f"(c[0]), "+f"(c[1]), "+f"(c[2]), "+f"(c[3])
        : "r"(a[0]), "r"(a[1]), "r"(a[2]), "r"(a[3]), "r"(b[0]), "r"(b[1]));
}

// ---------------- K0: zero output --------------------------------------------
__global__ void zero_kernel(float4* __restrict__ out) {
    int idx = blockIdx.x * blockDim.x + threadIdx.x;
#pragma unroll
    for (int i = 0; i < 4; i++)
        out[idx + i * 1048576] = make_float4(0.f, 0.f, 0.f, 0.f);
}

// ---------------- K1: router (fp32 GEMM + top-2 + softmax) --------------------
__global__ void router_kernel(const float* __restrict__ x,
                              const float* __restrict__ Wr,
                              const float* __restrict__ br) {
    __shared__ float xs[16][64];
    __shared__ float ws[16][64];
    __shared__ float sm[64 * 65];

    const int tid = threadIdx.x;
    const int tx = tid & 15, ty = tid >> 4;
    const int tok0 = blockIdx.x * 64;
    const int lt = tid >> 2, lq = tid & 3;
    const int wd = tid >> 4, we = (tid & 15) * 4;

    float acc[4][4] = {};
    for (int d0 = 0; d0 < DIM; d0 += 16) {
        float4 xv = *(const float4*)&x[(size_t)(tok0 + lt) * DIM + d0 + lq * 4];
        float4 wv = *(const float4*)&Wr[(size_t)(d0 + wd) * NEXP + we];
        __syncthreads();
        xs[lq * 4 + 0][lt] = xv.x; xs[lq * 4 + 1][lt] = xv.y;
        xs[lq * 4 + 2][lt] = xv.z; xs[lq * 4 + 3][lt] = xv.w;
        *(float4*)&ws[wd][we] = wv;
        __syncthreads();
#pragma unroll
        for (int kk = 0; kk < 16; kk++) {
            float a[4], b[4];
#pragma unroll
            for (int i = 0; i < 4; i++) a[i] = xs[kk][ty * 4 + i];
#pragma unroll
            for (int j = 0; j < 4; j++) b[j] = ws[kk][tx * 4 + j];
#pragma unroll
            for (int i = 0; i < 4; i++)
#pragma unroll
                for (int j = 0; j < 4; j++) acc[i][j] += a[i] * b[j];
        }
    }
    __syncthreads();
#pragma unroll
    for (int i = 0; i < 4; i++)
#pragma unroll
        for (int j = 0; j < 4; j++)
            sm[(ty * 4 + i) * 65 + tx * 4 + j] = acc[i][j] + br[tx * 4 + j];
    __syncthreads();

    if (tid < 64) {
        const int t = tid;
        float v1 = -3.402823466e+38f, v2 = -3.402823466e+38f;
        int i1 = 0, i2 = 0;
#pragma unroll 4
        for (int e = 0; e < NEXP; e++) {
            float v = sm[t * 65 + e];
            if (v > v1) { v2 = v1; i2 = i1; v1 = v; i1 = e; }
            else if (v > v2) { v2 = v; i2 = e; }
        }
        float texp = expf(v2 - v1);
        float inv = 1.f / (1.f + texp);
        int n = tok0 + t;
        g_ef[n]         = i1;
        g_ef[N_TOK + n] = i2;
        g_gf[n]         = inv;
        g_gf[N_TOK + n] = texp * inv;
    }
}

// ---------------- K2: coalesced ballot-based per-expert slot scan --------------
// One block per expert; processes the k-major flat ordering in 1024-entry tiles
// with lane-contiguous loads, preserving the reference cumsum order exactly.
__global__ void scan_kernel() {
    const int e = blockIdx.x;
    const int tid = threadIdx.x;          // 256
    const int lane = tid & 31, w = tid >> 5;   // 8 warps
    __shared__ int warp_tot[32];          // [sub 0..3][warp 0..7]
    __shared__ int sub_base[33];          // exclusive scan of the 32 totals
    __shared__ int run_base;
    if (tid == 0) run_base = 0;
    __syncthreads();

    for (int t = 0; t < 32; t++) {
        const int base = t * 1024;
        int ef[4];
#pragma unroll
        for (int s = 0; s < 4; s++) ef[s] = g_ef[base + s * 256 + tid];
        unsigned m[4];
#pragma unroll
        for (int s = 0; s < 4; s++) {
            m[s] = __ballot_sync(0xffffffffu, ef[s] == e);
            if (lane == 0) warp_tot[s * 8 + w] = __popc(m[s]);
        }
        __syncthreads();                  // A: warp_tot visible
        if (w == 0) {
            int v = warp_tot[lane];
#pragma unroll
            for (int off = 1; off < 32; off <<= 1) {
                int u = __shfl_up_sync(0xffffffffu, v, off);
                if (lane >= off) v += u;
            }
            sub_base[lane + 1] = v;
            if (lane == 0) sub_base[0] = 0;
        }
        __syncthreads();                  // B: sub_base visible
        const int rb = run_base;
        const int tile_tot = sub_base[32];
#pragma unroll
        for (int s = 0; s < 4; s++) {
            if (ef[s] == e) {
                int rank = rb + sub_base[s * 8 + w] +
                           __popc(m[s] & ((1u << lane) - 1u));
                if (rank < CAP) {
                    int f = base + s * 256 + tid;
                    g_slot_tok[e * CAP + rank]  = (f >= N_TOK) ? f - N_TOK : f;
                    g_slot_gate[e * CAP + rank] = g_gf[f];
                }
            }
        }
        __syncthreads();                  // C: all read rb before update
        if (tid == 0) run_base = rb + tile_tot;
    }
    if (tid == 0) g_cnt[e] = run_base;
}

// ---------------- K3a: convert+transpose We -> fp16 [e][n][k] -----------------
__global__ void convW_kernel(const float* __restrict__ We) {
    __shared__ float s[32][65];   // [h][d]
    const int e = blockIdx.z;
    const int h0 = blockIdx.x * 32, d0 = blockIdx.y * 64;
    const int tx = threadIdx.x, ty = threadIdx.y;   // (32, 8)
    const float* W = We + (size_t)e * DIM * DIM;
#pragma unroll
    for (int j = 0; j < 8; j++) {
        int dd = ty + j * 8;
        s[tx][dd] = W[(size_t)(d0 + dd) * DIM + h0 + tx];
    }
    __syncthreads();
#pragma unroll
    for (int j = 0; j < 4; j++) {
        int hh = ty + j * 8;
        __half2 hv = __floats2half2_rn(s[hh][2 * tx], s[hh][2 * tx + 1]);
        *(__half2*)(g_B + (size_t)e * DIM * DIM + (size_t)(h0 + hh) * DIM +
                    d0 + 2 * tx) = hv;
    }
}

// ---------------- K3b: pack dispatched token rows -> fp16 ---------------------
__global__ void packA_kernel(const float* __restrict__ x) {
    const int row = blockIdx.x;              // e*CAP + slot
    const int e = row / CAP, s = row % CAP;
    if (s >= min(g_cnt[e], CAP)) return;
    const int tok = g_slot_tok[row];
    const int t = threadIdx.x * 8;           // 128 threads x 8 elems
    const float4* src = (const float4*)(x + (size_t)tok * DIM + t);
    float4 f0 = src[0], f1 = src[1];
    uint4 u;
    __half2* ph = (__half2*)&u;
    ph[0] = __floats2half2_rn(f0.x, f0.y);
    ph[1] = __floats2half2_rn(f0.z, f0.w);
    ph[2] = __floats2half2_rn(f1.x, f1.y);
    ph[3] = __floats2half2_rn(f1.z, f1.w);
    *(uint4*)(g_A + (size_t)row * DIM + t) = u;
}

// ---------------- K4: mma.sync fp16 grouped GEMM + fused gated ReLU combine ---
// 128x256 CTA tile, 512 threads (16 warps, 2m x 8n of 64x32), 4-stage cp.async.
extern __shared__ __align__(128) char dsmem[];

__global__ void __launch_bounds__(512, 1)
moe_mma_kernel(float* __restrict__ out) {
    const int e = blockIdx.z;
    const int cnt = min(g_cnt[e], CAP);
    const int m0 = blockIdx.y * BM;
    if (m0 >= cnt) return;
    const int n0 = blockIdx.x * BN;
    const int tid = threadIdx.x;
    const int lane = tid & 31, wid = tid >> 5;
    const int wm = (wid & 1) * 64, wn = (wid >> 1) * 32;

    __shared__ int   tok_s[BM];
    __shared__ float gate_s[BM];
    if (tid < BM) {
        int r = m0 + tid;
        bool v = r < cnt;
        tok_s[tid]  = v ? g_slot_tok[e * CAP + r] : 0;
        gate_s[tid] = v ? g_slot_gate[e * CAP + r] : 0.f;
    }

    const uint32_t sbase = smem_u32(dsmem);
    const __half* Ag = g_A + ((size_t)e * CAP + m0) * DIM;
    const __half* Bg = g_B + ((size_t)e * DIM + n0) * DIM;

    // loaders: A 512x16B (1/thread), B 1024x16B (2/thread); 80 B smem rows
    const int ar = tid >> 2, aq = tid & 3;

#define LOAD_STAGE(s, kc) do {                                                \
        uint32_t sA = sbase + (s) * STG;                                      \
        uint32_t sB = sA + A_STG;                                             \
        const __half* Ak = Ag + (kc) * KC;                                    \
        const __half* Bk = Bg + (kc) * KC;                                    \
        cp16(sA + ar * 80 + aq * 16, Ak + (size_t)ar * DIM + aq * 8);         \
        cp16(sB + ar * 80 + aq * 16, Bk + (size_t)ar * DIM + aq * 8);         \
        cp16(sB + (ar + 128) * 80 + aq * 16,                                  \
             Bk + (size_t)(ar + 128) * DIM + aq * 8);                         \
    } while (0)

    LOAD_STAGE(0, 0); CP_COMMIT();
    LOAD_STAGE(1, 1); CP_COMMIT();
    LOAD_STAGE(2, 2); CP_COMMIT();

    float acc[4][4][4] = {};

    const uint32_t aoffs = (uint32_t)((wm + (lane & 15)) * 80 + (lane >> 4) * 16);
    const uint32_t boffs = (uint32_t)((wn + (lane & 7)) * 80 + ((lane >> 3) & 1) * 16);

    for (int kc = 0; kc < NK; kc++) {
        const int buf = kc & 3;
        asm volatile("cp.async.wait_group 2;" ::: "memory");
        __syncthreads();
        if (kc + 3 < NK) LOAD_STAGE((kc + 3) & 3, kc + 3);
        CP_COMMIT();

        const uint32_t sA = sbase + buf * STG;
        const uint32_t sB = sA + A_STG;
#pragma unroll
        for (int k16 = 0; k16 < KC; k16 += 16) {
            uint32_t a[4][4], b[4][2];
#pragma unroll
            for (int mi = 0; mi < 4; mi++)
                ldsm_x4(a[mi], sA + aoffs + (uint32_t)(mi * 16 * 80 + k16 * 2));
#pragma unroll
            for (int ni = 0; ni < 4; ni++)
                ldsm_x2(b[ni], sB + boffs + (uint32_t)(ni * 8 * 80 + k16 * 2));
#pragma unroll
            for (int mi = 0; mi < 4; mi++)
#pragma unroll
                for (int ni = 0; ni < 4; ni++)
                    mma16816(acc[mi][ni], a[mi], b[ni]);
        }
    }

    // fused epilogue: out[token] += gate * relu(acc)  (<=2 contributions/elem)
#pragma unroll
    for (int mi = 0; mi < 4; mi++) {
        const int rbase = wm + mi * 16 + (lane >> 2);
#pragma unroll
        for (int h = 0; h < 2; h++) {
            const int rr = rbase + h * 8;
            if (m0 + rr < cnt) {
                const float g = gate_s[rr];
                float* orow = out + (size_t)tok_s[rr] * DIM + n0 + wn +
                              (lane & 3) * 2;
#pragma unroll
                for (int ni = 0; ni < 4; ni++) {
                    float2 v = make_float2(
                        g * fmaxf(acc[mi][ni][2 * h], 0.f),
                        g * fmaxf(acc[mi][ni][2 * h + 1], 0.f));
                    atomicAdd((float2*)(orow + ni * 8), v);
                }
            }
        }
    }
#undef LOAD_STAGE
}

// ---------------- launch ------------------------------------------------------
extern "C" void kernel_launch(void* const* d_in, const int* in_sizes, int n_in,
                              void* d_out, int out_size) {
    const float *x = nullptr, *Wr = nullptr, *br = nullptr, *We = nullptr;
    for (int i = 0; i < n_in; i++) {
        switch (in_sizes[i]) {
            case N_TOK * DIM: x  = (const float*)d_in[i]; break;
            case DIM * NEXP:  Wr = (const float*)d_in[i]; break;
            case NEXP:        br = (const float*)d_in[i]; break;
            default:
                if (in_sizes[i] == NEXP * DIM * DIM) We = (const float*)d_in[i];
                break;
        }
    }
    float* out = (float*)d_out;

    cudaFuncSetAttribute(moe_mma_kernel,
                         cudaFuncAttributeMaxDynamicSharedMemorySize, SMEM_BYTES);

    zero_kernel<<<4096, 256>>>((float4*)out);
    convW_kernel<<<dim3(32, 16, 64), dim3(32, 8)>>>(We);
    router_kernel<<<N_TOK / 64, 256>>>(x, Wr, br);
    scan_kernel<<<NEXP, 256>>>();
    packA_kernel<<<NEXP * CAP, 128>>>(x);
    dim3 grid(DIM / BN, (CAP + BM - 1) / BM, NEXP);   // 4 x 5 x 64
    moe_mma_kernel<<<grid, 512, SMEM_BYTES>>>(out);
}

// round 9
// speedup vs baseline: 3.9063x; 1.1121x over previous
#include <cuda_runtime.h>
#include <cuda_fp16.h>
#include <cstdint>

#define N_TOK   16384
#define DIM     1024
#define NEXP    64
#define CAP     640

#define BM 128
#define BN 256
#define KC 32
#define NK (DIM / KC)                 // 32 K-chunks
#define A_STG 10240                   // 128 rows * 80 B
#define B_STG 20480                   // 256 rows * 80 B
#define STG   (A_STG + B_STG)         // 30720
#define SMEM_BYTES (4 * STG)          // 122880, 4 stages

#define TILES 128                     // scan tiles over the 32768 flat entries
#define TSZ   256

// ---------------- persistent scratch ------------------------------------------
__device__ int   g_ef[2 * N_TOK];
__device__ float g_gf[2 * N_TOK];
__device__ int   g_slot_tok[NEXP * CAP];
__device__ float g_slot_gate[NEXP * CAP];
__device__ int   g_cnt[NEXP];
__device__ int   g_tile_hist[TILES * NEXP];
__device__ int   g_tile_base[TILES * NEXP];
__device__ __align__(1024) __half g_A[(size_t)NEXP * CAP * DIM];   // [e][slot][k]
__device__ __align__(1024) __half g_B[(size_t)NEXP * DIM * DIM];   // [e][n][k]

// ---------------- helpers -----------------------------------------------------
__device__ __forceinline__ uint32_t smem_u32(const void* p) {
    uint32_t a;
    asm("{ .reg .u64 t; cvta.to.shared.u64 t, %1; cvt.u32.u64 %0, t; }"
        : "=r"(a) : "l"(p));
    return a;
}
__device__ __forceinline__ void cp16(uint32_t s, const void* g) {
    asm volatile("cp.async.cg.shared.global [%0], [%1], 16;" :: "r"(s), "l"(g));
}
#define CP_COMMIT() asm volatile("cp.async.commit_group;" ::: "memory")

__device__ __forceinline__ void ldsm_x4(uint32_t* r, uint32_t addr) {
    asm volatile("ldmatrix.sync.aligned.m8n8.x4.shared.b16 {%0,%1,%2,%3}, [%4];"
                 : "=r"(r[0]), "=r"(r[1]), "=r"(r[2]), "=r"(r[3]) : "r"(addr));
}
__device__ __forceinline__ void ldsm_x2(uint32_t* r, uint32_t addr) {
    asm volatile("ldmatrix.sync.aligned.m8n8.x2.shared.b16 {%0,%1}, [%2];"
                 : "=r"(r[0]), "=r"(r[1]) : "r"(addr));
}
__device__ __forceinline__ void mma16816(float* c, const uint32_t* a,
                                         const uint32_t* b) {
    asm volatile(
        "mma.sync.aligned.m16n8k16.row.col.f32.f16.f16.f32 "
        "{%0,%1,%2,%3}, {%4,%5,%6,%7}, {%8,%9}, {%0,%1,%2,%3};"
        : "+f"(c[0]), "+f"(c[1]), "+f"(c[2]), "+f"(c[3])
        : "r"(a[0]), "r"(a[1]), "r"(a[2]), "r"(a[3]), "r"(b[0]), "r"(b[1]));
}

// ---------------- K1: FAT prelude: router | convW | zero ----------------------
// blocks [0,256):        router (64 tokens each)
// blocks [256,33024):    convW  (We fp32 -> g_B fp16 transposed [e][n][k])
// blocks [33024,34048):  zero   (d_out)
#define FAT_ROUTER 256
#define FAT_CONVW  (FAT_ROUTER + 32768)
#define FAT_TOTAL  (FAT_CONVW + 1024)

union FatSm {
    struct { float xs[16][64]; float ws[16][64]; float sm[64 * 65]; } r;
    float cw[32][65];
};

__global__ void __launch_bounds__(256)
fat_kernel(const float* __restrict__ x,
           const float* __restrict__ Wr,
           const float* __restrict__ br,
           const float* __restrict__ We,
           float4* __restrict__ out4) {
    __shared__ FatSm u;
    const int tid = threadIdx.x;
    const int bx = blockIdx.x;

    if (bx < FAT_ROUTER) {
        // ---- router: 64 tokens x 64 experts, fp32 ----
        const int tx = tid & 15, ty = tid >> 4;
        const int tok0 = bx * 64;
        const int lt = tid >> 2, lq = tid & 3;
        const int wd = tid >> 4, we = (tid & 15) * 4;

        float acc[4][4] = {};
        for (int d0 = 0; d0 < DIM; d0 += 16) {
            float4 xv = *(const float4*)&x[(size_t)(tok0 + lt) * DIM + d0 + lq * 4];
            float4 wv = *(const float4*)&Wr[(size_t)(d0 + wd) * NEXP + we];
            __syncthreads();
            u.r.xs[lq * 4 + 0][lt] = xv.x; u.r.xs[lq * 4 + 1][lt] = xv.y;
            u.r.xs[lq * 4 + 2][lt] = xv.z; u.r.xs[lq * 4 + 3][lt] = xv.w;
            *(float4*)&u.r.ws[wd][we] = wv;
            __syncthreads();
#pragma unroll
            for (int kk = 0; kk < 16; kk++) {
                float a[4], b[4];
#pragma unroll
                for (int i = 0; i < 4; i++) a[i] = u.r.xs[kk][ty * 4 + i];
#pragma unroll
                for (int j = 0; j < 4; j++) b[j] = u.r.ws[kk][tx * 4 + j];
#pragma unroll
                for (int i = 0; i < 4; i++)
#pragma unroll
                    for (int j = 0; j < 4; j++) acc[i][j] += a[i] * b[j];
            }
        }
        __syncthreads();
#pragma unroll
        for (int i = 0; i < 4; i++)
#pragma unroll
            for (int j = 0; j < 4; j++)
                u.r.sm[(ty * 4 + i) * 65 + tx * 4 + j] = acc[i][j] + br[tx * 4 + j];
        __syncthreads();

        if (tid < 64) {
            const int t = tid;
            float v1 = -3.402823466e+38f, v2 = -3.402823466e+38f;
            int i1 = 0, i2 = 0;
#pragma unroll 4
            for (int e = 0; e < NEXP; e++) {
                float v = u.r.sm[t * 65 + e];
                if (v > v1) { v2 = v1; i2 = i1; v1 = v; i1 = e; }
                else if (v > v2) { v2 = v; i2 = e; }
            }
            float texp = expf(v2 - v1);
            float inv = 1.f / (1.f + texp);
            int n = tok0 + t;
            g_ef[n]         = i1;
            g_ef[N_TOK + n] = i2;
            g_gf[n]         = inv;
            g_gf[N_TOK + n] = texp * inv;
        }
    } else if (bx < FAT_CONVW) {
        // ---- convW: transpose + fp16 convert ----
        const int cb = bx - FAT_ROUTER;       // 0..32767
        const int e = cb >> 9;                // /512
        const int r = cb & 511;
        const int h0 = (r & 31) * 32;
        const int d0 = (r >> 5) * 64;
        const int tx = tid & 31, ty = tid >> 5;   // (32, 8)
        const float* W = We + (size_t)e * DIM * DIM;
#pragma unroll
        for (int j = 0; j < 8; j++) {
            int dd = ty + j * 8;
            u.cw[tx][dd] = W[(size_t)(d0 + dd) * DIM + h0 + tx];
        }
        __syncthreads();
#pragma unroll
        for (int j = 0; j < 4; j++) {
            int hh = ty + j * 8;
            __half2 hv = __floats2half2_rn(u.cw[hh][2 * tx], u.cw[hh][2 * tx + 1]);
            *(__half2*)(g_B + (size_t)e * DIM * DIM + (size_t)(h0 + hh) * DIM +
                        d0 + 2 * tx) = hv;
        }
    } else {
        // ---- zero d_out: 1024 blocks x 256 thr x 16 float4 = 64MB ----
        const int zb = bx - FAT_CONVW;
        const int base = zb * 256 + tid;      // 0..262143
#pragma unroll
        for (int i = 0; i < 16; i++)
            out4[base + i * 262144] = make_float4(0.f, 0.f, 0.f, 0.f);
    }
}

// ---------------- K2a: per-tile expert histograms -----------------------------
__global__ void __launch_bounds__(TSZ)
scanA_kernel() {
    __shared__ int hist[NEXP];
    const int t = blockIdx.x, tid = threadIdx.x;
    if (tid < NEXP) hist[tid] = 0;
    __syncthreads();
    const int e = g_ef[t * TSZ + tid];
    atomicAdd(&hist[e], 1);
    __syncthreads();
    if (tid < NEXP) g_tile_hist[t * NEXP + tid] = hist[tid];
}

// ---------------- K2b: per-expert exclusive prefix over tiles -----------------
__global__ void __launch_bounds__(1024)
scanB_kernel() {
    const int tid = threadIdx.x;
    const int lane = tid & 31, w = tid >> 5;   // 32 warps
    for (int e = w; e < NEXP; e += 32) {
        int c[4];
#pragma unroll
        for (int j = 0; j < 4; j++)
            c[j] = g_tile_hist[(lane * 4 + j) * NEXP + e];
        int lsum = c[0] + c[1] + c[2] + c[3];
        int v = lsum;
#pragma unroll
        for (int off = 1; off < 32; off <<= 1) {
            int uu = __shfl_up_sync(0xffffffffu, v, off);
            if (lane >= off) v += uu;
        }
        int run = v - lsum;                    // exclusive prefix for this lane
#pragma unroll
        for (int j = 0; j < 4; j++) {
            g_tile_base[(lane * 4 + j) * NEXP + e] = run;
            run += c[j];
        }
        if (lane == 31) g_cnt[e] = run;
    }
}

// ---------------- K2c: rank + scatter + fused fp16 row pack -------------------
// Threads 0..255 compute order-preserving ranks for the tile's 256 entries
// (warp segments ascending in f, lanes ascending); all 512 threads then pack
// kept token rows x[tok] -> g_A[e*CAP+rank] in fp16 (2 rows in flight).
__global__ void __launch_bounds__(512)
scanC_kernel(const float* __restrict__ x) {
    __shared__ int seg[8 * NEXP];          // [warpSeg][expert] count -> base
    __shared__ int l_dst[TSZ];
    __shared__ int l_tok[TSZ];
    __shared__ int nkeep;
    const int t = blockIdx.x, tid = threadIdx.x;
    const int lane = tid & 31, w = tid >> 5;

    if (tid < 512) { /* always true; keeps indexing clear */ }
    if (tid < 8 * NEXP) seg[tid] = 0;
    if (tid == 0) nkeep = 0;
    __syncthreads();

    if (tid < TSZ) {
        const int f = t * TSZ + tid;
        const int e = g_ef[f];
        unsigned m = __match_any_sync(0xffffffffu, e);
        int leader = __ffs(m) - 1;
        int rin = __popc(m & ((1u << lane) - 1u));
        if (lane == leader) seg[w * NEXP + e] = __popc(m);
        __syncthreads();
        if (tid < NEXP) {                   // per-expert prefix over 8 segments
            int vals[8];
#pragma unroll
            for (int s = 0; s < 8; s++) vals[s] = seg[s * NEXP + tid];
            int base = 0;
#pragma unroll
            for (int s = 0; s < 8; s++) { seg[s * NEXP + tid] = base; base += vals[s]; }
        }
        __syncthreads();
        const int rank = g_tile_base[t * NEXP + e] + seg[w * NEXP + e] + rin;
        if (rank < CAP) {
            const int tok = (f >= N_TOK) ? f - N_TOK : f;
            const int dst = e * CAP + rank;
            g_slot_tok[dst]  = tok;
            g_slot_gate[dst] = g_gf[f];
            int i = atomicAdd(&nkeep, 1);
            l_dst[i] = dst;
            l_tok[i] = tok;
        }
    } else {
        __syncthreads();
        __syncthreads();
    }
    __syncthreads();

    const int nk = nkeep;
    const int half = tid >> 8;              // 0 or 1: two rows in flight
    const int c = tid & 255;                // float4 index within row
    for (int i = half; i < nk; i += 2) {
        const float4 v = ((const float4*)(x + (size_t)l_tok[i] * DIM))[c];
        __half2 h0 = __floats2half2_rn(v.x, v.y);
        __half2 h1 = __floats2half2_rn(v.z, v.w);
        __half2* dst = (__half2*)(g_A + (size_t)l_dst[i] * DIM) + 2 * c;
        dst[0] = h0;
        dst[1] = h1;
    }
}

// ---------------- K4: mma.sync fp16 grouped GEMM + fused gated ReLU combine ---
extern __shared__ __align__(128) char dsmem[];

__global__ void __launch_bounds__(512, 1)
moe_mma_kernel(float* __restrict__ out) {
    const int e = blockIdx.z;
    const int cnt = min(g_cnt[e], CAP);
    const int m0 = blockIdx.y * BM;
    if (m0 >= cnt) return;
    const int n0 = blockIdx.x * BN;
    const int tid = threadIdx.x;
    const int lane = tid & 31, wid = tid >> 5;
    const int wm = (wid & 1) * 64, wn = (wid >> 1) * 32;

    __shared__ int   tok_s[BM];
    __shared__ float gate_s[BM];
    if (tid < BM) {
        int r = m0 + tid;
        bool v = r < cnt;
        tok_s[tid]  = v ? g_slot_tok[e * CAP + r] : 0;
        gate_s[tid] = v ? g_slot_gate[e * CAP + r] : 0.f;
    }

    const uint32_t sbase = smem_u32(dsmem);
    const __half* Ag = g_A + ((size_t)e * CAP + m0) * DIM;
    const __half* Bg = g_B + ((size_t)e * DIM + n0) * DIM;

    const int ar = tid >> 2, aq = tid & 3;

#define LOAD_STAGE(s, kc) do {                                                \
        uint32_t sA = sbase + (s) * STG;                                      \
        uint32_t sB = sA + A_STG;                                             \
        const __half* Ak = Ag + (kc) * KC;                                    \
        const __half* Bk = Bg + (kc) * KC;                                    \
        cp16(sA + ar * 80 + aq * 16, Ak + (size_t)ar * DIM + aq * 8);         \
        cp16(sB + ar * 80 + aq * 16, Bk + (size_t)ar * DIM + aq * 8);         \
        cp16(sB + (ar + 128) * 80 + aq * 16,                                  \
             Bk + (size_t)(ar + 128) * DIM + aq * 8);                         \
    } while (0)

    LOAD_STAGE(0, 0); CP_COMMIT();
    LOAD_STAGE(1, 1); CP_COMMIT();
    LOAD_STAGE(2, 2); CP_COMMIT();

    float acc[4][4][4] = {};

    const uint32_t aoffs = (uint32_t)((wm + (lane & 15)) * 80 + (lane >> 4) * 16);
    const uint32_t boffs = (uint32_t)((wn + (lane & 7)) * 80 + ((lane >> 3) & 1) * 16);

    for (int kc = 0; kc < NK; kc++) {
        const int buf = kc & 3;
        asm volatile("cp.async.wait_group 2;" ::: "memory");
        __syncthreads();
        if (kc + 3 < NK) LOAD_STAGE((kc + 3) & 3, kc + 3);
        CP_COMMIT();

        const uint32_t sA = sbase + buf * STG;
        const uint32_t sB = sA + A_STG;
#pragma unroll
        for (int k16 = 0; k16 < KC; k16 += 16) {
            uint32_t a[4][4], b[4][2];
#pragma unroll
            for (int mi = 0; mi < 4; mi++)
                ldsm_x4(a[mi], sA + aoffs + (uint32_t)(mi * 16 * 80 + k16 * 2));
#pragma unroll
            for (int ni = 0; ni < 4; ni++)
                ldsm_x2(b[ni], sB + boffs + (uint32_t)(ni * 8 * 80 + k16 * 2));
#pragma unroll
            for (int mi = 0; mi < 4; mi++)
#pragma unroll
                for (int ni = 0; ni < 4; ni++)
                    mma16816(acc[mi][ni], a[mi], b[ni]);
        }
    }

#pragma unroll
    for (int mi = 0; mi < 4; mi++) {
        const int rbase = wm + mi * 16 + (lane >> 2);
#pragma unroll
        for (int h = 0; h < 2; h++) {
            const int rr = rbase + h * 8;
            if (m0 + rr < cnt) {
                const float g = gate_s[rr];
                float* orow = out + (size_t)tok_s[rr] * DIM + n0 + wn +
                              (lane & 3) * 2;
#pragma unroll
                for (int ni = 0; ni < 4; ni++) {
                    float2 v = make_float2(
                        g * fmaxf(acc[mi][ni][2 * h], 0.f),
                        g * fmaxf(acc[mi][ni][2 * h + 1], 0.f));
                    atomicAdd((float2*)(orow + ni * 8), v);
                }
            }
        }
    }
#undef LOAD_STAGE
}

// ---------------- launch ------------------------------------------------------
extern "C" void kernel_launch(void* const* d_in, const int* in_sizes, int n_in,
                              void* d_out, int out_size) {
    const float *x = nullptr, *Wr = nullptr, *br = nullptr, *We = nullptr;
    for (int i = 0; i < n_in; i++) {
        switch (in_sizes[i]) {
            case N_TOK * DIM: x  = (const float*)d_in[i]; break;
            case DIM * NEXP:  Wr = (const float*)d_in[i]; break;
            case NEXP:        br = (const float*)d_in[i]; break;
            default:
                if (in_sizes[i] == NEXP * DIM * DIM) We = (const float*)d_in[i];
                break;
        }
    }
    float* out = (float*)d_out;

    cudaFuncSetAttribute(moe_mma_kernel,
                         cudaFuncAttributeMaxDynamicSharedMemorySize, SMEM_BYTES);

    fat_kernel<<<FAT_TOTAL, 256>>>(x, Wr, br, We, (float4*)out);
    scanA_kernel<<<TILES, TSZ>>>();
    scanB_kernel<<<1, 1024>>>();
    scanC_kernel<<<TILES, 512>>>(x);
    dim3 grid(DIM / BN, (CAP + BM - 1) / BM, NEXP);   // 4 x 5 x 64
    moe_mma_kernel<<<grid, 512, SMEM_BYTES>>>(out);
}

// round 12
// speedup vs baseline: 3.9776x; 1.0183x over previous
#include <cuda_runtime.h>
#include <cuda_fp16.h>
#include <cstdint>

#define N_TOK   16384
#define DIM     1024
#define NEXP    64
#define CAP     640

#define BM 128
#define BN 256
#define KC 32
#define NK (DIM / KC)                 // 32 K-chunks
#define A_STG 10240                   // 128 rows * 80 B
#define B_STG 20480                   // 256 rows * 80 B
#define STG   (A_STG + B_STG)         // 30720
#define SMEM_BYTES (4 * STG)          // 122880, 4 stages

#define TILES 128                     // scan tiles over the 32768 flat entries
#define TSZ   256

// ---------------- persistent scratch ------------------------------------------
__device__ int   g_ef[2 * N_TOK];
__device__ float g_gf[2 * N_TOK];
__device__ int   g_slot_tok[NEXP * CAP];
__device__ float g_slot_gate[NEXP * CAP];
__device__ int   g_cnt[NEXP];
__device__ int   g_tile_base[TILES * NEXP];
__device__ int   g_tile_hist[TILES * NEXP];
__device__ __align__(1024) __half g_xh[(size_t)N_TOK * DIM];       // fp16 x, token-indexed
__device__ __align__(1024) __half g_B[(size_t)NEXP * DIM * DIM];   // [e][n][k]

// ---------------- helpers -----------------------------------------------------
__device__ __forceinline__ uint32_t smem_u32(const void* p) {
    uint32_t a;
    asm("{ .reg .u64 t; cvta.to.shared.u64 t, %1; cvt.u32.u64 %0, t; }"
        : "=r"(a) : "l"(p));
    return a;
}
__device__ __forceinline__ void cp16(uint32_t s, const void* g) {
    asm volatile("cp.async.cg.shared.global [%0], [%1], 16;" :: "r"(s), "l"(g));
}
#define CP_COMMIT() asm volatile("cp.async.commit_group;" ::: "memory")

__device__ __forceinline__ void ldsm_x4(uint32_t* r, uint32_t addr) {
    asm volatile("ldmatrix.sync.aligned.m8n8.x4.shared.b16 {%0,%1,%2,%3}, [%4];"
                 : "=r"(r[0]), "=r"(r[1]), "=r"(r[2]), "=r"(r[3]) : "r"(addr));
}
__device__ __forceinline__ void ldsm_x2(uint32_t* r, uint32_t addr) {
    asm volatile("ldmatrix.sync.aligned.m8n8.x2.shared.b16 {%0,%1}, [%2];"
                 : "=r"(r[0]), "=r"(r[1]) : "r"(addr));
}
__device__ __forceinline__ void mma16816(float* c, const uint32_t* a,
                                         const uint32_t* b) {
    asm volatile(
        "mma.sync.aligned.m16n8k16.row.col.f32.f16.f16.f32 "
        "{%0,%1,%2,%3}, {%4,%5,%6,%7}, {%8,%9}, {%0,%1,%2,%3};"
        : "+f"(c[0]), "+f"(c[1]), "+f"(c[2]), "+f"(c[3])
        : "r"(a[0]), "r"(a[1]), "r"(a[2]), "r"(a[3]), "r"(b[0]), "r"(b[1]));
}

// ---------------- K1: FAT prelude: router(+x->fp16) | convW | zero ------------
#define FAT_ROUTER 256
#define FAT_CONVW  (FAT_ROUTER + 32768)
#define FAT_TOTAL  (FAT_CONVW + 1024)

union FatSm {
    struct { float xs[16][64]; float ws[16][64]; float sm[64 * 65]; } r;
    float cw[32][65];
};

__global__ void __launch_bounds__(256)
fat_kernel(const float* __restrict__ x,
           const float* __restrict__ Wr,
           const float* __restrict__ br,
           const float* __restrict__ We,
           float4* __restrict__ out4) {
    __shared__ FatSm u;
    const int tid = threadIdx.x;
    const int bx = blockIdx.x;

    if (bx < FAT_ROUTER) {
        // ---- router: 64 tokens x 64 experts fp32; also emit g_xh fp16 copy ----
        const int tx = tid & 15, ty = tid >> 4;
        const int tok0 = bx * 64;
        const int lt = tid >> 2, lq = tid & 3;
        const int wd = tid >> 4, we = (tid & 15) * 4;

        float acc[4][4] = {};
        for (int d0 = 0; d0 < DIM; d0 += 16) {
            float4 xv = *(const float4*)&x[(size_t)(tok0 + lt) * DIM + d0 + lq * 4];
            float4 wv = *(const float4*)&Wr[(size_t)(d0 + wd) * NEXP + we];
            // free fp16 conversion of x while it's in registers
            {
                uint2 pk;
                ((__half2*)&pk)[0] = __floats2half2_rn(xv.x, xv.y);
                ((__half2*)&pk)[1] = __floats2half2_rn(xv.z, xv.w);
                *(uint2*)(g_xh + (size_t)(tok0 + lt) * DIM + d0 + lq * 4) = pk;
            }
            __syncthreads();
            u.r.xs[lq * 4 + 0][lt] = xv.x; u.r.xs[lq * 4 + 1][lt] = xv.y;
            u.r.xs[lq * 4 + 2][lt] = xv.z; u.r.xs[lq * 4 + 3][lt] = xv.w;
            *(float4*)&u.r.ws[wd][we] = wv;
            __syncthreads();
#pragma unroll
            for (int kk = 0; kk < 16; kk++) {
                float a[4], b[4];
#pragma unroll
                for (int i = 0; i < 4; i++) a[i] = u.r.xs[kk][ty * 4 + i];
#pragma unroll
                for (int j = 0; j < 4; j++) b[j] = u.r.ws[kk][tx * 4 + j];
#pragma unroll
                for (int i = 0; i < 4; i++)
#pragma unroll
                    for (int j = 0; j < 4; j++) acc[i][j] += a[i] * b[j];
            }
        }
        __syncthreads();
#pragma unroll
        for (int i = 0; i < 4; i++)
#pragma unroll
            for (int j = 0; j < 4; j++)
                u.r.sm[(ty * 4 + i) * 65 + tx * 4 + j] = acc[i][j] + br[tx * 4 + j];
        __syncthreads();

        if (tid < 64) {
            const int t = tid;
            float v1 = -3.402823466e+38f, v2 = -3.402823466e+38f;
            int i1 = 0, i2 = 0;
#pragma unroll 4
            for (int e = 0; e < NEXP; e++) {
                float v = u.r.sm[t * 65 + e];
                if (v > v1) { v2 = v1; i2 = i1; v1 = v; i1 = e; }
                else if (v > v2) { v2 = v; i2 = e; }
            }
            float texp = expf(v2 - v1);
            float inv = 1.f / (1.f + texp);
            int n = tok0 + t;
            g_ef[n]         = i1;
            g_ef[N_TOK + n] = i2;
            g_gf[n]         = inv;
            g_gf[N_TOK + n] = texp * inv;
        }
    } else if (bx < FAT_CONVW) {
        // ---- convW: transpose + fp16 convert ----
        const int cb = bx - FAT_ROUTER;       // 0..32767
        const int e = cb >> 9;
        const int r = cb & 511;
        const int h0 = (r & 31) * 32;
        const int d0 = (r >> 5) * 64;
        const int tx = tid & 31, ty = tid >> 5;   // (32, 8)
        const float* W = We + (size_t)e * DIM * DIM;
#pragma unroll
        for (int j = 0; j < 8; j++) {
            int dd = ty + j * 8;
            u.cw[tx][dd] = W[(size_t)(d0 + dd) * DIM + h0 + tx];
        }
        __syncthreads();
#pragma unroll
        for (int j = 0; j < 4; j++) {
            int hh = ty + j * 8;
            __half2 hv = __floats2half2_rn(u.cw[hh][2 * tx], u.cw[hh][2 * tx + 1]);
            *(__half2*)(g_B + (size_t)e * DIM * DIM + (size_t)(h0 + hh) * DIM +
                        d0 + 2 * tx) = hv;
        }
    } else {
        // ---- zero d_out ----
        const int zb = bx - FAT_CONVW;
        const int base = zb * 256 + tid;
#pragma unroll
        for (int i = 0; i < 16; i++)
            out4[base + i * 262144] = make_float4(0.f, 0.f, 0.f, 0.f);
    }
}

// ---------------- K2a: per-tile expert histograms -----------------------------
__global__ void __launch_bounds__(TSZ)
scanA_kernel() {
    __shared__ int hist[NEXP];
    const int t = blockIdx.x, tid = threadIdx.x;
    if (tid < NEXP) hist[tid] = 0;
    __syncthreads();
    const int e = g_ef[t * TSZ + tid];
    atomicAdd(&hist[e], 1);
    __syncthreads();
    if (tid < NEXP) g_tile_hist[t * NEXP + tid] = hist[tid];
}

// ---------------- K2b: per-expert exclusive prefix over tiles -----------------
__global__ void __launch_bounds__(1024)
scanB_kernel() {
    const int tid = threadIdx.x;
    const int lane = tid & 31, w = tid >> 5;   // 32 warps
    for (int e = w; e < NEXP; e += 32) {
        int c[4];
#pragma unroll
        for (int j = 0; j < 4; j++)
            c[j] = g_tile_hist[(lane * 4 + j) * NEXP + e];
        int lsum = c[0] + c[1] + c[2] + c[3];
        int v = lsum;
#pragma unroll
        for (int off = 1; off < 32; off <<= 1) {
            int uu = __shfl_up_sync(0xffffffffu, v, off);
            if (lane >= off) v += uu;
        }
        int run = v - lsum;
#pragma unroll
        for (int j = 0; j < 4; j++) {
            g_tile_base[(lane * 4 + j) * NEXP + e] = run;
            run += c[j];
        }
        if (lane == 31) g_cnt[e] = run;
    }
}

// ---------------- K2c: order-preserving rank + scatter (no pack) --------------
__global__ void __launch_bounds__(TSZ)
scanC_kernel() {
    __shared__ int seg[8 * NEXP];          // [warpSeg][expert] count -> base
    const int t = blockIdx.x, tid = threadIdx.x;
    const int lane = tid & 31, w = tid >> 5;

    for (int i = tid; i < 8 * NEXP; i += TSZ) seg[i] = 0;
    __syncthreads();

    const int f = t * TSZ + tid;
    const int e = g_ef[f];
    unsigned m = __match_any_sync(0xffffffffu, e);
    int leader = __ffs(m) - 1;
    int rin = __popc(m & ((1u << lane) - 1u));
    if (lane == leader) seg[w * NEXP + e] = __popc(m);
    __syncthreads();
    if (tid < NEXP) {                       // per-expert prefix over 8 segments
        int vals[8];
#pragma unroll
        for (int s = 0; s < 8; s++) vals[s] = seg[s * NEXP + tid];
        int base = 0;
#pragma unroll
        for (int s = 0; s < 8; s++) { seg[s * NEXP + tid] = base; base += vals[s]; }
    }
    __syncthreads();
    const int rank = g_tile_base[t * NEXP + e] + seg[w * NEXP + e] + rin;
    if (rank < CAP) {
        g_slot_tok[e * CAP + rank]  = (f >= N_TOK) ? f - N_TOK : f;
        g_slot_gate[e * CAP + rank] = g_gf[f];
    }
}

// ---------------- K4: mma.sync fp16 gather-A GEMM + fused gated ReLU combine --
extern __shared__ __align__(128) char dsmem[];

__global__ void __launch_bounds__(512, 1)
moe_mma_kernel(float* __restrict__ out) {
    const int e = blockIdx.z;
    const int cnt = min(g_cnt[e], CAP);
    const int m0 = blockIdx.y * BM;
    if (m0 >= cnt) return;
    const int n0 = blockIdx.x * BN;
    const int tid = threadIdx.x;
    const int lane = tid & 31, wid = tid >> 5;
    const int wm = (wid & 1) * 64, wn = (wid >> 1) * 32;

    __shared__ int   tok_s[BM];
    __shared__ float gate_s[BM];
    if (tid < BM) {
        int r = m0 + tid;
        bool v = r < cnt;
        tok_s[tid]  = v ? g_slot_tok[e * CAP + r] : 0;
        gate_s[tid] = v ? g_slot_gate[e * CAP + r] : 0.f;
    }
    __syncthreads();                        // tok_s ready for gather loaders

    const uint32_t sbase = smem_u32(dsmem);
    const __half* Bg = g_B + ((size_t)e * DIM + n0) * DIM;

    // loaders: A 512x16B gathered per-row from g_xh, B 1024x16B; 80 B smem rows
    const int ar = tid >> 2, aq = tid & 3;
    const __half* Arow = g_xh + (size_t)tok_s[ar] * DIM + aq * 8;

#define LOAD_STAGE(s, kc) do {                                                \
        uint32_t sA = sbase + (s) * STG;                                      \
        uint32_t sB = sA + A_STG;                                             \
        const __half* Bk = Bg + (kc) * KC;                                    \
        cp16(sA + ar * 80 + aq * 16, Arow + (kc) * KC);                       \
        cp16(sB + ar * 80 + aq * 16, Bk + (size_t)ar * DIM + aq * 8);         \
        cp16(sB + (ar + 128) * 80 + aq * 16,                                  \
             Bk + (size_t)(ar + 128) * DIM + aq * 8);                         \
    } while (0)

    LOAD_STAGE(0, 0); CP_COMMIT();
    LOAD_STAGE(1, 1); CP_COMMIT();
    LOAD_STAGE(2, 2); CP_COMMIT();

    float acc[4][4][4] = {};

    const uint32_t aoffs = (uint32_t)((wm + (lane & 15)) * 80 + (lane >> 4) * 16);
    const uint32_t boffs = (uint32_t)((wn + (lane & 7)) * 80 + ((lane >> 3) & 1) * 16);

    for (int kc = 0; kc < NK; kc++) {
        const int buf = kc & 3;
        asm volatile("cp.async.wait_group 2;" ::: "memory");
        __syncthreads();
        if (kc + 3 < NK) LOAD_STAGE((kc + 3) & 3, kc + 3);
        CP_COMMIT();

        const uint32_t sA = sbase + buf * STG;
        const uint32_t sB = sA + A_STG;
#pragma unroll
        for (int k16 = 0; k16 < KC; k16 += 16) {
            uint32_t a[4][4], b[4][2];
#pragma unroll
            for (int mi = 0; mi < 4; mi++)
                ldsm_x4(a[mi], sA + aoffs + (uint32_t)(mi * 16 * 80 + k16 * 2));
#pragma unroll
            for (int ni = 0; ni < 4; ni++)
                ldsm_x2(b[ni], sB + boffs + (uint32_t)(ni * 8 * 80 + k16 * 2));
#pragma unroll
            for (int mi = 0; mi < 4; mi++)
#pragma unroll
                for (int ni = 0; ni < 4; ni++)
                    mma16816(acc[mi][ni], a[mi], b[ni]);
        }
    }

#pragma unroll
    for (int mi = 0; mi < 4; mi++) {
        const int rbase = wm + mi * 16 + (lane >> 2);
#pragma unroll
        for (int h = 0; h < 2; h++) {
            const int rr = rbase + h * 8;
            if (m0 + rr < cnt) {
                const float g = gate_s[rr];
                float* orow = out + (size_t)tok_s[rr] * DIM + n0 + wn +
                              (lane & 3) * 2;
#pragma unroll
                for (int ni = 0; ni < 4; ni++) {
                    float2 v = make_float2(
                        g * fmaxf(acc[mi][ni][2 * h], 0.f),
                        g * fmaxf(acc[mi][ni][2 * h + 1], 0.f));
                    atomicAdd((float2*)(orow + ni * 8), v);
                }
            }
        }
    }
#undef LOAD_STAGE
}

// ---------------- launch ------------------------------------------------------
extern "C" void kernel_launch(void* const* d_in, const int* in_sizes, int n_in,
                              void* d_out, int out_size) {
    const float *x = nullptr, *Wr = nullptr, *br = nullptr, *We = nullptr;
    for (int i = 0; i < n_in; i++) {
        switch (in_sizes[i]) {
            case N_TOK * DIM: x  = (const float*)d_in[i]; break;
            case DIM * NEXP:  Wr = (const float*)d_in[i]; break;
            case NEXP:        br = (const float*)d_in[i]; break;
            default:
                if (in_sizes[i] == NEXP * DIM * DIM) We = (const float*)d_in[i];
                break;
        }
    }
    float* out = (float*)d_out;

    cudaFuncSetAttribute(moe_mma_kernel,
                         cudaFuncAttributeMaxDynamicSharedMemorySize, SMEM_BYTES);

    fat_kernel<<<FAT_TOTAL, 256>>>(x, Wr, br, We, (float4*)out);
    scanA_kernel<<<TILES, TSZ>>>();
    scanB_kernel<<<1, 1024>>>();
    scanC_kernel<<<TILES, TSZ>>>();
    dim3 grid(DIM / BN, (CAP + BM - 1) / BM, NEXP);   // 4 x 5 x 64
    moe_mma_kernel<<<grid, 512, SMEM_BYTES>>>(out);
}

// round 14
// speedup vs baseline: 4.1738x; 1.0493x over previous
#include <cuda_runtime.h>
#include <cuda_fp16.h>
#include <cstdint>

#define N_TOK   16384
#define DIM     1024
#define NEXP    64
#define CAP     640

#define BM 128
#define BN 256
#define KC 32
#define NK (DIM / KC)                 // 32 K-chunks
#define A_STG 10240                   // 128 rows * 80 B
#define RS    528                     // B smem row stride: 512 B data + 16 pad
#define B_STG (32 * RS)               // 16896
#define STG   (A_STG + B_STG)         // 27136
#define SMEM_BYTES (4 * STG)          // 108544, 4 stages

#define TILES 128
#define TSZ   256

// ---------------- persistent scratch ------------------------------------------
__device__ int   g_ef[2 * N_TOK];
__device__ float g_gf[2 * N_TOK];
__device__ int   g_slot_tok[NEXP * CAP];
__device__ float g_slot_gate[NEXP * CAP];
__device__ int   g_cnt[NEXP];
__device__ int   g_tile_base[TILES * NEXP];
__device__ int   g_tile_hist[TILES * NEXP];   // statically zero; scanB re-zeroes
__device__ __align__(1024) __half g_xh[(size_t)N_TOK * DIM];  // fp16 x, token-indexed

// ---------------- helpers -----------------------------------------------------
__device__ __forceinline__ uint32_t smem_u32(const void* p) {
    uint32_t a;
    asm("{ .reg .u64 t; cvta.to.shared.u64 t, %1; cvt.u32.u64 %0, t; }"
        : "=r"(a) : "l"(p));
    return a;
}
__device__ __forceinline__ void cp16(uint32_t s, const void* g) {
    asm volatile("cp.async.cg.shared.global [%0], [%1], 16;" :: "r"(s), "l"(g));
}
#define CP_COMMIT() asm volatile("cp.async.commit_group;" ::: "memory")

__device__ __forceinline__ void ldsm_x4(uint32_t* r, uint32_t addr) {
    asm volatile("ldmatrix.sync.aligned.m8n8.x4.shared.b16 {%0,%1,%2,%3}, [%4];"
                 : "=r"(r[0]), "=r"(r[1]), "=r"(r[2]), "=r"(r[3]) : "r"(addr));
}
__device__ __forceinline__ void ldsm_x2_trans(uint32_t* r, uint32_t addr) {
    asm volatile("ldmatrix.sync.aligned.m8n8.x2.trans.shared.b16 {%0,%1}, [%2];"
                 : "=r"(r[0]), "=r"(r[1]) : "r"(addr));
}
__device__ __forceinline__ void mma16816(float* c, const uint32_t* a,
                                         const uint32_t* b) {
    asm volatile(
        "mma.sync.aligned.m16n8k16.row.col.f32.f16.f16.f32 "
        "{%0,%1,%2,%3}, {%4,%5,%6,%7}, {%8,%9}, {%0,%1,%2,%3};"
        : "+f"(c[0]), "+f"(c[1]), "+f"(c[2]), "+f"(c[3])
        : "r"(a[0]), "r"(a[1]), "r"(a[2]), "r"(a[3]), "r"(b[0]), "r"(b[1]));
}

// ---------------- K1: FAT prelude: router(+x->fp16, +tile hist) | zero --------
#define FAT_ROUTER 256
#define FAT_TOTAL  (FAT_ROUTER + 1024)

__global__ void __launch_bounds__(256)
fat_kernel(const float* __restrict__ x,
           const float* __restrict__ Wr,
           const float* __restrict__ br,
           float4* __restrict__ out4) {
    __shared__ float xs[16][64];
    __shared__ float ws[16][64];
    __shared__ float sm[64 * 65];
    const int tid = threadIdx.x;
    const int bx = blockIdx.x;

    if (bx < FAT_ROUTER) {
        const int tx = tid & 15, ty = tid >> 4;
        const int tok0 = bx * 64;
        const int lt = tid >> 2, lq = tid & 3;
        const int wd = tid >> 4, we = (tid & 15) * 4;

        float acc[4][4] = {};
        for (int d0 = 0; d0 < DIM; d0 += 16) {
            float4 xv = *(const float4*)&x[(size_t)(tok0 + lt) * DIM + d0 + lq * 4];
            float4 wv = *(const float4*)&Wr[(size_t)(d0 + wd) * NEXP + we];
            {   // free fp16 conversion of x while it's in registers
                uint2 pk;
                ((__half2*)&pk)[0] = __floats2half2_rn(xv.x, xv.y);
                ((__half2*)&pk)[1] = __floats2half2_rn(xv.z, xv.w);
                *(uint2*)(g_xh + (size_t)(tok0 + lt) * DIM + d0 + lq * 4) = pk;
            }
            __syncthreads();
            xs[lq * 4 + 0][lt] = xv.x; xs[lq * 4 + 1][lt] = xv.y;
            xs[lq * 4 + 2][lt] = xv.z; xs[lq * 4 + 3][lt] = xv.w;
            *(float4*)&ws[wd][we] = wv;
            __syncthreads();
#pragma unroll
            for (int kk = 0; kk < 16; kk++) {
                float a[4], b[4];
#pragma unroll
                for (int i = 0; i < 4; i++) a[i] = xs[kk][ty * 4 + i];
#pragma unroll
                for (int j = 0; j < 4; j++) b[j] = ws[kk][tx * 4 + j];
#pragma unroll
                for (int i = 0; i < 4; i++)
#pragma unroll
                    for (int j = 0; j < 4; j++) acc[i][j] += a[i] * b[j];
            }
        }
        __syncthreads();
#pragma unroll
        for (int i = 0; i < 4; i++)
#pragma unroll
            for (int j = 0; j < 4; j++)
                sm[(ty * 4 + i) * 65 + tx * 4 + j] = acc[i][j] + br[tx * 4 + j];
        __syncthreads();

        if (tid < 64) {
            const int t = tid;
            float v1 = -3.402823466e+38f, v2 = -3.402823466e+38f;
            int i1 = 0, i2 = 0;
#pragma unroll 4
            for (int e = 0; e < NEXP; e++) {
                float v = sm[t * 65 + e];
                if (v > v1) { v2 = v1; i2 = i1; v1 = v; i1 = e; }
                else if (v > v2) { v2 = v; i2 = e; }
            }
            float texp = expf(v2 - v1);
            float inv = 1.f / (1.f + texp);
            int n = tok0 + t;
            g_ef[n]         = i1;
            g_ef[N_TOK + n] = i2;
            g_gf[n]         = inv;
            g_gf[N_TOK + n] = texp * inv;
            // fused scanA: per-tile histograms (hist is zero at launch entry)
            atomicAdd(&g_tile_hist[(n >> 8) * NEXP + i1], 1);
            atomicAdd(&g_tile_hist[((n >> 8) + 64) * NEXP + i2], 1);
        }
    } else {
        const int zb = bx - FAT_ROUTER;
        const int base = zb * 256 + tid;
#pragma unroll
        for (int i = 0; i < 16; i++)
            out4[base + i * 262144] = make_float4(0.f, 0.f, 0.f, 0.f);
    }
}

// ---------------- K2b: per-expert exclusive prefix over tiles (+hist reset) ---
__global__ void __launch_bounds__(1024)
scanB_kernel() {
    const int tid = threadIdx.x;
    const int lane = tid & 31, w = tid >> 5;   // 32 warps
    for (int e = w; e < NEXP; e += 32) {
        int c[4];
#pragma unroll
        for (int j = 0; j < 4; j++)
            c[j] = g_tile_hist[(lane * 4 + j) * NEXP + e];
        int lsum = c[0] + c[1] + c[2] + c[3];
        int v = lsum;
#pragma unroll
        for (int off = 1; off < 32; off <<= 1) {
            int uu = __shfl_up_sync(0xffffffffu, v, off);
            if (lane >= off) v += uu;
        }
        int run = v - lsum;
#pragma unroll
        for (int j = 0; j < 4; j++) {
            g_tile_base[(lane * 4 + j) * NEXP + e] = run;
            run += c[j];
            g_tile_hist[(lane * 4 + j) * NEXP + e] = 0;  // reset for next replay
        }
        if (lane == 31) g_cnt[e] = run;
    }
}

// ---------------- K2c: order-preserving rank + scatter ------------------------
__global__ void __launch_bounds__(TSZ)
scanC_kernel() {
    __shared__ int seg[8 * NEXP];
    const int t = blockIdx.x, tid = threadIdx.x;
    const int lane = tid & 31, w = tid >> 5;

    for (int i = tid; i < 8 * NEXP; i += TSZ) seg[i] = 0;
    __syncthreads();

    const int f = t * TSZ + tid;
    const int e = g_ef[f];
    unsigned m = __match_any_sync(0xffffffffu, e);
    int leader = __ffs(m) - 1;
    int rin = __popc(m & ((1u << lane) - 1u));
    if (lane == leader) seg[w * NEXP + e] = __popc(m);
    __syncthreads();
    if (tid < NEXP) {
        int vals[8];
#pragma unroll
        for (int s = 0; s < 8; s++) vals[s] = seg[s * NEXP + tid];
        int base = 0;
#pragma unroll
        for (int s = 0; s < 8; s++) { seg[s * NEXP + tid] = base; base += vals[s]; }
    }
    __syncthreads();
    const int rank = g_tile_base[t * NEXP + e] + seg[w * NEXP + e] + rin;
    if (rank < CAP) {
        g_slot_tok[e * CAP + rank]  = (f >= N_TOK) ? f - N_TOK : f;
        g_slot_gate[e * CAP + rank] = g_gf[f];
    }
}

// ---------------- K4: GEMM, A gathered fp16, B converted from We in-kernel ----
extern __shared__ __align__(128) char dsmem[];

__global__ void __launch_bounds__(512, 1)
moe_mma_kernel(const float* __restrict__ We, float* __restrict__ out) {
    const int e = blockIdx.z;
    const int cnt = min(g_cnt[e], CAP);
    const int m0 = blockIdx.y * BM;
    if (m0 >= cnt) return;
    const int n0 = blockIdx.x * BN;
    const int tid = threadIdx.x;
    const int lane = tid & 31, wid = tid >> 5;
    const int wm = (wid & 1) * 64, wn = (wid >> 1) * 32;

    __shared__ int   tok_s[BM];
    __shared__ float gate_s[BM];
    if (tid < BM) {
        int r = m0 + tid;
        bool v = r < cnt;
        tok_s[tid]  = v ? g_slot_tok[e * CAP + r] : 0;
        gate_s[tid] = v ? g_slot_gate[e * CAP + r] : 0.f;
    }
    __syncthreads();

    const uint32_t sbase = smem_u32(dsmem);

    // ---- A loader (cp.async, gathered): 512 x 16B per stage --------------------
    const int ar = tid >> 2, aq = tid & 3;
    const __half* Arow = g_xh + (size_t)tok_s[ar] * DIM + aq * 8;
#define CPA(s, kc) cp16(sbase + (s) * STG + ar * 80 + aq * 16, Arow + (kc) * KC)

    // ---- B loader (LDG fp32 -> cvt -> STS fp16), [k][n] rows, no transpose -----
    const int kr = tid >> 4, nc = tid & 15;       // 32 rows x 16 col-threads
    const float* Bld = We + (size_t)e * DIM * DIM + (size_t)kr * DIM + n0 + nc * 8;
    float4 breg[4];
#define LDG_B(kc) do {                                                        \
        const float4* p = (const float4*)(Bld + (size_t)(kc) * KC * DIM);     \
        breg[0] = p[0]; breg[1] = p[1];          /* chunk nc      */          \
        breg[2] = p[32]; breg[3] = p[33];        /* chunk nc+16   */          \
    } while (0)
#define STS_B(s) do {                                                         \
        char* sp = dsmem + (s) * STG + A_STG + kr * RS + nc * 16;             \
        uint4 u0, u1;                                                         \
        ((__half2*)&u0)[0] = __floats2half2_rn(breg[0].x, breg[0].y);         \
        ((__half2*)&u0)[1] = __floats2half2_rn(breg[0].z, breg[0].w);         \
        ((__half2*)&u0)[2] = __floats2half2_rn(breg[1].x, breg[1].y);         \
        ((__half2*)&u0)[3] = __floats2half2_rn(breg[1].z, breg[1].w);         \
        ((__half2*)&u1)[0] = __floats2half2_rn(breg[2].x, breg[2].y);         \
        ((__half2*)&u1)[1] = __floats2half2_rn(breg[2].z, breg[2].w);         \
        ((__half2*)&u1)[2] = __floats2half2_rn(breg[3].x, breg[3].y);         \
        ((__half2*)&u1)[3] = __floats2half2_rn(breg[3].z, breg[3].w);         \
        *(uint4*)sp = u0;                                                     \
        *(uint4*)(sp + 256) = u1;                                             \
    } while (0)

    // prologue: A async stages 0..2; B stages 0,1 staged, stage 2 in regs
    CPA(0, 0); CP_COMMIT();
    CPA(1, 1); CP_COMMIT();
    CPA(2, 2); CP_COMMIT();
    LDG_B(0); STS_B(0);
    LDG_B(1); STS_B(1);
    LDG_B(2);

    float acc[4][4][4] = {};

    const uint32_t aoffs = (uint32_t)((wm + (lane & 15)) * 80 + (lane >> 4) * 16);
    const uint32_t btr   = (uint32_t)(A_STG + (lane & 15) * RS + wn * 2);

    for (int kc = 0; kc < NK; kc++) {
        const int buf = kc & 3;
        if (kc + 2 < NK) STS_B((kc + 2) & 3);   // stage written 2 ahead; safe
        if (kc + 3 < NK) LDG_B(kc + 3);
        asm volatile("cp.async.wait_group 2;" ::: "memory");
        __syncthreads();
        if (kc + 3 < NK) CPA((kc + 3) & 3, kc + 3);
        CP_COMMIT();

        const uint32_t sA = sbase + buf * STG;
        const uint32_t sBt = sA + btr;
#pragma unroll
        for (int k16 = 0; k16 < KC; k16 += 16) {
            uint32_t a[4][4], b[4][2];
#pragma unroll
            for (int mi = 0; mi < 4; mi++)
                ldsm_x4(a[mi], sA + aoffs + (uint32_t)(mi * 16 * 80 + k16 * 2));
#pragma unroll
            for (int ni = 0; ni < 4; ni++)
                ldsm_x2_trans(b[ni], sBt + (uint32_t)(k16 * RS + ni * 16));
#pragma unroll
            for (int mi = 0; mi < 4; mi++)
#pragma unroll
                for (int ni = 0; ni < 4; ni++)
                    mma16816(acc[mi][ni], a[mi], b[ni]);
        }
    }

    // fused epilogue: out[token] += gate * relu(acc)
#pragma unroll
    for (int mi = 0; mi < 4; mi++) {
        const int rbase = wm + mi * 16 + (lane >> 2);
#pragma unroll
        for (int h = 0; h < 2; h++) {
            const int rr = rbase + h * 8;
            if (m0 + rr < cnt) {
                const float g = gate_s[rr];
                float* orow = out + (size_t)tok_s[rr] * DIM + n0 + wn +
                              (lane & 3) * 2;
#pragma unroll
                for (int ni = 0; ni < 4; ni++) {
                    float2 v = make_float2(
                        g * fmaxf(acc[mi][ni][2 * h], 0.f),
                        g * fmaxf(acc[mi][ni][2 * h + 1], 0.f));
                    atomicAdd((float2*)(orow + ni * 8), v);
                }
            }
        }
    }
#undef CPA
#undef LDG_B
#undef STS_B
}

// ---------------- launch ------------------------------------------------------
extern "C" void kernel_launch(void* const* d_in, const int* in_sizes, int n_in,
                              void* d_out, int out_size) {
    const float *x = nullptr, *Wr = nullptr, *br = nullptr, *We = nullptr;
    for (int i = 0; i < n_in; i++) {
        switch (in_sizes[i]) {
            case N_TOK * DIM: x  = (const float*)d_in[i]; break;
            case DIM * NEXP:  Wr = (const float*)d_in[i]; break;
            case NEXP:        br = (const float*)d_in[i]; break;
            default:
                if (in_sizes[i] == NEXP * DIM * DIM) We = (const float*)d_in[i];
                break;
        }
    }
    float* out = (float*)d_out;

    cudaFuncSetAttribute(moe_mma_kernel,
                         cudaFuncAttributeMaxDynamicSharedMemorySize, SMEM_BYTES);

    fat_kernel<<<FAT_TOTAL, 256>>>(x, Wr, br, (float4*)out);
    scanB_kernel<<<1, 1024>>>();
    scanC_kernel<<<TILES, TSZ>>>();
    dim3 grid(DIM / BN, (CAP + BM - 1) / BM, NEXP);   // 4 x 5 x 64
    moe_mma_kernel<<<grid, 512, SMEM_BYTES>>>(We, out);
}